// round 6
// baseline (speedup 1.0000x reference)
#include <cuda_runtime.h>
#include <cuda_bf16.h>
#include <math.h>

// Problem constants
#define Fn 500
#define Hn 2000
#define FH 2500
#define Dn 64
#define An 64
#define Bn 4096
#define NB 444       // 3 CTAs/SM x 148 SMs: all co-resident -> grid barrier safe

// Scratch (device globals; no allocation allowed)
__device__ __align__(16) float g_pre_f[Fn * Dn];
__device__ __align__(16) float g_pre_w[FH * Dn];
__device__ __align__(16) float g_ctx  [Fn * Dn];
__device__ float g_pwmax[FH];

// Replay-safe sense-reversing grid barrier (count self-resets, gen monotonic)
__device__ unsigned g_count = 0;
__device__ unsigned g_gen   = 0;

__device__ __forceinline__ void grid_bar() {
    __threadfence();
    __syncthreads();
    if (threadIdx.x == 0) {
        unsigned gen = atomicAdd(&g_gen, 0u);
        if (atomicAdd(&g_count, 1u) == NB - 1u) {
            g_count = 0u;
            __threadfence();
            atomicAdd(&g_gen, 1u);
        } else {
            while (atomicAdd(&g_gen, 0u) == gen) __nanosleep(32);
        }
    }
    __syncthreads();
}

// ---------------- packed f32x2 helpers (Blackwell) ----------------
typedef unsigned long long ull;
__device__ __forceinline__ ull pk2(float a, float b) {
    ull r; asm("mov.b64 %0, {%1,%2};" : "=l"(r) : "f"(a), "f"(b)); return r;
}
__device__ __forceinline__ void upk2(ull v, float& a, float& b) {
    asm("mov.b64 {%0,%1}, %2;" : "=f"(a), "=f"(b) : "l"(v));
}
__device__ __forceinline__ ull f2fma(ull a, ull b, ull c) {
    ull d; asm("fma.rn.f32x2 %0, %1, %2, %3;" : "=l"(d) : "l"(a), "l"(b), "l"(c)); return d;
}
__device__ __forceinline__ ull f2mul(ull a, ull b) {
    ull d; asm("mul.rn.f32x2 %0, %1, %2;" : "=l"(d) : "l"(a), "l"(b)); return d;
}

__device__ __forceinline__ const float* full_row(const float* feat,
                                                 const float* hid, int j) {
    return (j < Fn) ? (feat + j * Dn) : (hid + (j - Fn) * Dn);
}

// ---------------- shared memory union across stages ----------------
#define TFk 50
struct __align__(16) S1 {
    float sx[4][Dn];
    float m[8];
};
struct __align__(16) S2 {
    float pf[Dn];
    float wu[Dn];
    float elist[FH];
    unsigned short jlist[FH];
    int   warpbase[9];
    float wsum[8];
    float red8[8];
    float part[4][Dn];
    float pfmax;
    float inv;
    int   needexact;
};
struct __align__(16) S3 {
    float val[16][TFk];
    float ctx[TFk][Dn];
};
union SMem { S1 s1; S2 s2; S3 s3; };

// ---------------------------------------------------------------------------
__global__ __launch_bounds__(256, 3) void fused_all(
    const float* __restrict__ values,
    const float* __restrict__ feat,
    const float* __restrict__ hid,
    const float* __restrict__ Ww,
    const float* __restrict__ bw,
    const float* __restrict__ Wu,
    const float* __restrict__ mask,
    float* __restrict__ out)
{
    __shared__ SMem sm;
    const int tid  = threadIdx.x;
    const int wid  = tid >> 5;
    const int lane = tid & 31;

    // ============ Stage 1: pre_w = full@W2 (+pwmax); pre_f = feat@W1+bw ======
    {
        const int g = tid >> 6;     // row within task (0..3)
        const int a = tid & 63;     // output column
        for (int t = blockIdx.x; t < 750; t += NB) {
            __syncthreads();
            if (t < 625) {
                const int row = t * 4 + g;                  // 0..2499
                float v = (row < Fn) ? feat[row * Dn + a]
                                     : hid[(row - Fn) * Dn + a];
                sm.s1.sx[g][a] = v;
                __syncthreads();
                float acc = 0.f;
                #pragma unroll
                for (int k = 0; k < Dn; k++)
                    acc += sm.s1.sx[g][k] * __ldg(&Ww[(Dn + k) * An + a]);
                g_pre_w[row * Dn + a] = acc;
                float mm = fabsf(acc);
                #pragma unroll
                for (int off = 16; off > 0; off >>= 1)
                    mm = fmaxf(mm, __shfl_xor_sync(0xffffffffu, mm, off));
                if (lane == 0) sm.s1.m[wid] = mm;
                __syncthreads();
                if (tid < 4)
                    g_pwmax[t * 4 + tid] =
                        fmaxf(sm.s1.m[2 * tid], sm.s1.m[2 * tid + 1]);
            } else {
                const int row = (t - 625) * 4 + g;          // 0..499
                sm.s1.sx[g][a] = feat[row * Dn + a];
                __syncthreads();
                float acc = __ldg(&bw[a]);
                #pragma unroll
                for (int k = 0; k < Dn; k++)
                    acc += sm.s1.sx[g][k] * __ldg(&Ww[k * An + a]);
                g_pre_f[row * Dn + a] = acc;
            }
        }
    }

    grid_bar();

    // ============ Stage 2: masked attention -> ctx ===========================
    for (int i = blockIdx.x; i < Fn; i += NB) {
        __syncthreads();
        if (tid < Dn) {
            sm.s2.pf[tid] = g_pre_f[i * Dn + tid];
            sm.s2.wu[tid] = __ldg(&Wu[tid]);
        }
        __syncthreads();

        if (wid == 0) {
            float m = fmaxf(fabsf(sm.s2.pf[lane]), fabsf(sm.s2.pf[lane + 32]));
            #pragma unroll
            for (int off = 16; off > 0; off >>= 1)
                m = fmaxf(m, __shfl_xor_sync(0xffffffffu, m, off));
            if (lane == 0) sm.s2.pfmax = m;
        }

        // ---- Phase A: single-pass deterministic compaction
        const float* mrow = mask + (size_t)i * FH;
        unsigned flags = 0;
        #pragma unroll
        for (int c = 0; c < 10; c++) {
            int j = c * 256 + tid;
            if (j < FH && mrow[j] != 0.0f) flags |= (1u << c);
        }
        const int cl = __popc(flags);
        int inc = cl;
        #pragma unroll
        for (int off = 1; off < 32; off <<= 1) {
            int v = __shfl_up_sync(0xffffffffu, inc, off);
            if (lane >= off) inc += v;
        }
        if (lane == 31) sm.s2.warpbase[wid + 1] = inc;
        __syncthreads();
        if (tid == 0) {
            sm.s2.warpbase[0] = 0;
            #pragma unroll
            for (int w = 1; w <= 8; w++)
                sm.s2.warpbase[w] += sm.s2.warpbase[w - 1];
        }
        __syncthreads();
        {
            int off = sm.s2.warpbase[wid] + inc - cl;
            #pragma unroll
            for (int c = 0; c < 10; c++)
                if ((flags >> c) & 1u)
                    sm.s2.jlist[off++] = (unsigned short)(c * 256 + tid);
        }
        __syncthreads();
        const int cnt = sm.s2.warpbase[8];

        // ---- block-level exact-path flag (hoists branch out of hot loop)
        {
            float mx = 0.f;
            for (int m = tid; m < cnt; m += 256)
                mx = fmaxf(mx, __ldg(&g_pwmax[(int)sm.s2.jlist[m]]));
            #pragma unroll
            for (int off = 16; off > 0; off >>= 1)
                mx = fmaxf(mx, __shfl_xor_sync(0xffffffffu, mx, off));
            if (lane == 0) sm.s2.red8[wid] = mx;
            __syncthreads();
            if (tid == 0) {
                float m2 = 0.f;
                #pragma unroll
                for (int w = 0; w < 8; w++) m2 = fmaxf(m2, sm.s2.red8[w]);
                sm.s2.needexact = (sm.s2.pfmax + m2 > 0.45f) ? 1 : 0;
            }
            __syncthreads();
        }

        // ---- Phase B: thread-per-item (MLP 16, no shuffles in hot loop)
        const ull C3  = pk2(-0.33333334f, -0.33333334f);
        const ull C5  = pk2( 0.13333334f,  0.13333334f);
        const ull C7  = pk2(-0.05396825f, -0.05396825f);
        const ull ONE = pk2(1.0f, 1.0f);
        const float4* pf4 = (const float4*)sm.s2.pf;
        const float4* wu4 = (const float4*)sm.s2.wu;
        float wsum = 0.f;

        if (!sm.s2.needexact) {
            for (int m = tid; m < cnt; m += 256) {
                const int j = sm.s2.jlist[m];
                const float4* pr = (const float4*)(g_pre_w + j * Dn);
                ull acc = 0ull;
                #pragma unroll
                for (int q = 0; q < 16; q++) {
                    float4 pw = __ldg(pr + q);
                    float4 pf = pf4[q];
                    float4 wu = wu4[q];
                    ull x01 = pk2(pf.x + pw.x, pf.y + pw.y);
                    ull x23 = pk2(pf.z + pw.z, pf.w + pw.w);
                    ull t01 = f2mul(x01, x01);
                    ull t23 = f2mul(x23, x23);
                    ull p01 = f2fma(t01, C7, C5);
                    ull p23 = f2fma(t23, C7, C5);
                    p01 = f2fma(t01, p01, C3);
                    p23 = f2fma(t23, p23, C3);
                    p01 = f2fma(t01, p01, ONE);
                    p23 = f2fma(t23, p23, ONE);
                    acc = f2fma(f2mul(x01, p01), pk2(wu.x, wu.y), acc);
                    acc = f2fma(f2mul(x23, p23), pk2(wu.z, wu.w), acc);
                }
                float a0, a1; upk2(acc, a0, a1);
                float e = __expf(a0 + a1);
                sm.s2.elist[m] = e;
                wsum += e;
            }
        } else {
            // rare exact path (adversarial magnitudes)
            for (int m = tid; m < cnt; m += 256) {
                const int j = sm.s2.jlist[m];
                const float* pr = g_pre_w + j * Dn;
                float s = 0.f;
                for (int k = 0; k < Dn; k++)
                    s += tanhf(sm.s2.pf[k] + pr[k]) * sm.s2.wu[k];
                float e = expf(s);
                sm.s2.elist[m] = e;
                wsum += e;
            }
        }
        #pragma unroll
        for (int off = 16; off > 0; off >>= 1)
            wsum += __shfl_xor_sync(0xffffffffu, wsum, off);
        if (lane == 0) sm.s2.wsum[wid] = wsum;
        __syncthreads();
        if (tid == 0) {
            float ss = 0.f;
            #pragma unroll
            for (int w = 0; w < 8; w++) ss += sm.s2.wsum[w];
            sm.s2.inv = (ss > 0.f) ? (1.0f / ss) : 1.0f;
        }
        __syncthreads();

        // ---- Phase C: context accumulation (8 independent chains, MLP 8)
        {
            const int g = tid >> 6;
            const int k = tid & 63;
            float a0 = 0.f, a1 = 0.f, a2 = 0.f, a3 = 0.f;
            float a4 = 0.f, a5 = 0.f, a6 = 0.f, a7 = 0.f;
            int m = g;
            for (; m + 28 < cnt; m += 32) {
                a0 += sm.s2.elist[m]      * __ldg(full_row(feat, hid, sm.s2.jlist[m])      + k);
                a1 += sm.s2.elist[m + 4]  * __ldg(full_row(feat, hid, sm.s2.jlist[m + 4])  + k);
                a2 += sm.s2.elist[m + 8]  * __ldg(full_row(feat, hid, sm.s2.jlist[m + 8])  + k);
                a3 += sm.s2.elist[m + 12] * __ldg(full_row(feat, hid, sm.s2.jlist[m + 12]) + k);
                a4 += sm.s2.elist[m + 16] * __ldg(full_row(feat, hid, sm.s2.jlist[m + 16]) + k);
                a5 += sm.s2.elist[m + 20] * __ldg(full_row(feat, hid, sm.s2.jlist[m + 20]) + k);
                a6 += sm.s2.elist[m + 24] * __ldg(full_row(feat, hid, sm.s2.jlist[m + 24]) + k);
                a7 += sm.s2.elist[m + 28] * __ldg(full_row(feat, hid, sm.s2.jlist[m + 28]) + k);
            }
            for (; m < cnt; m += 4)
                a0 += sm.s2.elist[m] * __ldg(full_row(feat, hid, sm.s2.jlist[m]) + k);
            sm.s2.part[g][k] = ((a0 + a1) + (a2 + a3)) + ((a4 + a5) + (a6 + a7));
            __syncthreads();
            if (tid < Dn)
                g_ctx[i * Dn + tid] = (sm.s2.part[0][tid] + sm.s2.part[1][tid] +
                                       sm.s2.part[2][tid] + sm.s2.part[3][tid]) *
                                      sm.s2.inv;
        }
    }

    grid_bar();

    // ============ Stage 3: out = values @ ctx ================================
    if (blockIdx.x < 256) {
        const int tx   = tid & 15;
        const int ty   = tid >> 4;
        const int col0 = tx * 4;
        const int row  = blockIdx.x * 16 + ty;

        ull a0 = 0ull, a1 = 0ull;

        for (int f0 = 0; f0 < Fn; f0 += TFk) {
            for (int idx = tid; idx < 16 * TFk; idx += 256) {
                int r = idx / TFk, f = idx % TFk;
                sm.s3.val[r][f] = values[(size_t)(blockIdx.x * 16 + r) * Fn + f0 + f];
            }
            for (int idx = tid; idx < TFk * Dn; idx += 256) {
                int f = idx >> 6, c = idx & 63;
                sm.s3.ctx[f][c] = g_ctx[(f0 + f) * Dn + c];
            }
            __syncthreads();

            #pragma unroll
            for (int f = 0; f < TFk; f++) {
                float v = sm.s3.val[ty][f];
                ull vp = pk2(v, v);
                const ull* cp = reinterpret_cast<const ull*>(&sm.s3.ctx[f][col0]);
                a0 = f2fma(vp, cp[0], a0);
                a1 = f2fma(vp, cp[1], a1);
            }
            __syncthreads();
        }

        float a, b, c, d;
        upk2(a0, a, b); upk2(a1, c, d);
        *reinterpret_cast<float4*>(&out[(size_t)row * Dn + col0]) =
            make_float4(a, b, c, d);
    }
}

// ---------------------------------------------------------------------------
extern "C" void kernel_launch(void* const* d_in, const int* in_sizes, int n_in,
                              void* d_out, int out_size)
{
    const float* values   = (const float*)d_in[0];   // [4096,500]
    const float* feat_emb = (const float*)d_in[1];   // [500,64]
    const float* hid_emb  = (const float*)d_in[2];   // [2000,64]
    const float* Ww       = (const float*)d_in[3];   // [128,64]
    const float* bw       = (const float*)d_in[4];   // [64]
    const float* Wu       = (const float*)d_in[5];   // [64,1]
    const float* mask     = (const float*)d_in[6];   // [500,2500,1]
    float* out            = (float*)d_out;           // [4096,64]

    fused_all<<<NB, 256>>>(values, feat_emb, hid_emb, Ww, bw, Wu, mask, out);
}